// round 1
// baseline (speedup 1.0000x reference)
#include <cuda_runtime.h>
#include <math.h>

// Problem constants
#define B_   16
#define C_   256
#define N_   4096      // H*W = 64*64
#define HEADS 8
#define DH   32
#define QKV3 768       // 3*heads*dh
#define LN_EPS 1e-5f
#define L2_EPS 1e-12f
#define XC_SCALE 8.0f

// ---------------- scratch (static device globals; no allocation) ----------------
__device__ float g_t[(size_t)B_ * C_ * N_];        //  64 MB  LN'd input, [b][c][n]
__device__ float g_qkv[(size_t)B_ * QKV3 * N_];    // 192 MB  [b][j][n], j = sel*256 + h*32 + d
__device__ float g_qscale[B_ * C_];                // per (b, h*32+d): exp(temp[h]) / max(||q||,eps)
__device__ float g_kscale[B_ * C_];                // per (b, h*32+d): 1 / max(||k||,eps)
__device__ float g_attn[(size_t)B_ * HEADS * DH * DH];
__device__ float g_attnv[(size_t)B_ * C_ * N_];    //  64 MB  [b][h*32+d][n]

// ---------------- Kernel 1: LayerNorm over channel dim ----------------
// x: [b, c, n] (c-major). Thread -> one n; loop c (stride N_ -> coalesced across threads).
__global__ void ln_kernel(const float* __restrict__ x,
                          const float* __restrict__ gamma,
                          const float* __restrict__ beta) {
    int b = blockIdx.y;
    int n = blockIdx.x * blockDim.x + threadIdx.x;
    const float* xb = x + (size_t)b * C_ * N_ + n;
    float s = 0.f, s2 = 0.f;
    #pragma unroll 8
    for (int c = 0; c < C_; c++) {
        float v = xb[(size_t)c * N_];
        s += v; s2 += v * v;
    }
    float mu = s * (1.0f / C_);
    float var = s2 * (1.0f / C_) - mu * mu;
    float rstd = rsqrtf(var + LN_EPS);
    float* tb = g_t + (size_t)b * C_ * N_ + n;
    #pragma unroll 8
    for (int c = 0; c < C_; c++) {
        float v = xb[(size_t)c * N_];
        tb[(size_t)c * N_] = (v - mu) * rstd * gamma[c] + beta[c];
    }
}

// ---------------- Kernel 2/6: tiled fp32 GEMM ----------------
// C[b][j][n] = sum_k W[k*M_total + j] * Bm[b][k][n]  (+ bias[j])
// mode 0: Bm = g_t,    Cm = g_qkv      (M_total = 768)
// mode 1: Bm = g_attnv,Cm = out_ext    (M_total = 256, bias = b_out)
__global__ void gemm_kernel(const float* __restrict__ W,
                            const float* __restrict__ bias,
                            int M_total, int mode, float* __restrict__ out_ext) {
    const float* Bm = (mode == 0) ? g_t : g_attnv;
    float* Cm = (mode == 0) ? g_qkv : out_ext;
    const float* Bb = Bm + (size_t)blockIdx.z * C_ * N_;
    float* Cb = Cm + (size_t)blockIdx.z * M_total * N_;

    __shared__ float As[16][68];
    __shared__ float Bs[16][68];

    int tid = threadIdx.x;
    int tx = tid & 15, ty = tid >> 4;
    int n0 = blockIdx.x * 64;
    int j0 = blockIdx.y * 64;

    float acc[4][4] = {};

    for (int k0 = 0; k0 < C_; k0 += 16) {
        #pragma unroll
        for (int l = tid; l < 1024; l += 256) {
            int k = l >> 6, j = l & 63;
            As[k][j] = W[(size_t)(k0 + k) * M_total + j0 + j];
        }
        #pragma unroll
        for (int l = tid; l < 1024; l += 256) {
            int k = l >> 6, n = l & 63;
            Bs[k][n] = Bb[(size_t)(k0 + k) * N_ + n0 + n];
        }
        __syncthreads();
        #pragma unroll
        for (int kk = 0; kk < 16; kk++) {
            float4 a4 = *(const float4*)&As[kk][ty * 4];
            float4 b4 = *(const float4*)&Bs[kk][tx * 4];
            float av[4] = {a4.x, a4.y, a4.z, a4.w};
            float bv[4] = {b4.x, b4.y, b4.z, b4.w};
            #pragma unroll
            for (int r = 0; r < 4; r++)
                #pragma unroll
                for (int c = 0; c < 4; c++)
                    acc[r][c] += av[r] * bv[c];
        }
        __syncthreads();
    }

    #pragma unroll
    for (int r = 0; r < 4; r++) {
        int j = j0 + ty * 4 + r;
        float bi = bias ? bias[j] : 0.f;
        float4 o = make_float4(acc[r][0] + bi, acc[r][1] + bi, acc[r][2] + bi, acc[r][3] + bi);
        *(float4*)&Cb[(size_t)j * N_ + n0 + tx * 4] = o;
    }
}

// ---------------- Kernel 3: row L2 norms of q and k -> scale factors ----------------
// grid (256, 16, 2): x = hd index, y = b, z = which (0=q,1=k). 128 threads.
__global__ void norm_kernel(const float* __restrict__ temp) {
    int j = blockIdx.x, b = blockIdx.y, which = blockIdx.z;
    int tid = threadIdx.x;
    const float* row = g_qkv + ((size_t)b * QKV3 + which * 256 + j) * N_;
    float s = 0.f;
    for (int n = tid * 4; n < N_; n += 512) {
        float4 v = *(const float4*)&row[n];
        s += v.x * v.x + v.y * v.y + v.z * v.z + v.w * v.w;
    }
    #pragma unroll
    for (int o = 16; o > 0; o >>= 1) s += __shfl_down_sync(0xffffffffu, s, o);
    __shared__ float ws[4];
    if ((tid & 31) == 0) ws[tid >> 5] = s;
    __syncthreads();
    if (tid == 0) {
        float tot = ws[0] + ws[1] + ws[2] + ws[3];
        float d = fmaxf(sqrtf(tot), L2_EPS);
        float sc = (which == 0) ? (expf(temp[j >> 5]) / d) : (1.0f / d);
        if (which == 0) g_qscale[b * C_ + j] = sc;
        else            g_kscale[b * C_ + j] = sc;
    }
}

// ---------------- Kernel 4: sim = (q_n exp(t)) @ k_n^T * 8, softmax -> attn ----------------
// One block per (b,h). 256 threads = 4 K-split groups x 64 threads; each thread owns a
// 4x4 (i,j) tile; smem chunk of 128 n for q and k.
#define CHN 128
#define PAD 132
__global__ void sim_softmax_kernel() {
    __shared__ float qs[32 * PAD];
    __shared__ float ks[32 * PAD];
    __shared__ float simbuf[32 * 32];

    int bh = blockIdx.x;
    int b = bh >> 3, h = bh & 7;
    int tid = threadIdx.x;
    const float* qbase = g_qkv + ((size_t)b * QKV3 + h * DH) * N_;
    const float* kbase = g_qkv + ((size_t)b * QKV3 + 256 + h * DH) * N_;

    for (int l = tid; l < 1024; l += 256) simbuf[l] = 0.f;

    int g = tid >> 6;           // K-split group 0..3
    int p = tid & 63;
    int ii0 = (p >> 3) * 4;     // 0..28
    int jj0 = (p & 7) * 4;      // 0..28
    float acc[4][4] = {};

    for (int n0 = 0; n0 < N_; n0 += CHN) {
        for (int e = tid * 4; e < 32 * CHN; e += 1024) {
            int row = e >> 7, t = e & (CHN - 1);
            *(float4*)&qs[row * PAD + t] = *(const float4*)&qbase[(size_t)row * N_ + n0 + t];
            *(float4*)&ks[row * PAD + t] = *(const float4*)&kbase[(size_t)row * N_ + n0 + t];
        }
        __syncthreads();
        int tb = g * 32;
        #pragma unroll
        for (int s = 0; s < 8; s++) {
            int t = tb + s * 4;
            float4 qv[4], kv[4];
            #pragma unroll
            for (int r = 0; r < 4; r++) qv[r] = *(const float4*)&qs[(ii0 + r) * PAD + t];
            #pragma unroll
            for (int c = 0; c < 4; c++) kv[c] = *(const float4*)&ks[(jj0 + c) * PAD + t];
            #pragma unroll
            for (int r = 0; r < 4; r++)
                #pragma unroll
                for (int c = 0; c < 4; c++)
                    acc[r][c] += qv[r].x * kv[c].x + qv[r].y * kv[c].y
                               + qv[r].z * kv[c].z + qv[r].w * kv[c].w;
        }
        __syncthreads();
    }

    #pragma unroll
    for (int r = 0; r < 4; r++)
        #pragma unroll
        for (int c = 0; c < 4; c++)
            atomicAdd(&simbuf[(ii0 + r) * 32 + jj0 + c], acc[r][c]);
    __syncthreads();

    if (tid < 32) {
        int i = tid;
        float qsc = g_qscale[b * C_ + h * DH + i];
        float row[32];
        float mx = -1e30f;
        #pragma unroll
        for (int j = 0; j < 32; j++) {
            float v = simbuf[i * 32 + j] * qsc * g_kscale[b * C_ + h * DH + j] * XC_SCALE;
            row[j] = v;
            mx = fmaxf(mx, v);
        }
        float sum = 0.f;
        #pragma unroll
        for (int j = 0; j < 32; j++) { row[j] = expf(row[j] - mx); sum += row[j]; }
        float inv = 1.0f / sum;
        #pragma unroll
        for (int j = 0; j < 32; j++)
            g_attn[((size_t)bh * 32 + i) * 32 + j] = row[j] * inv;
    }
}

// ---------------- Kernel 5: out[b][hd][n] = attn @ v ----------------
// grid (N_/256, B_*HEADS); thread -> one n, 32 accumulators over i.
__global__ void av_kernel() {
    __shared__ float at[1024];
    int bh = blockIdx.y;
    int b = bh >> 3, h = bh & 7;
    int tid = threadIdx.x;
    int n = blockIdx.x * 256 + tid;

    for (int l = tid; l < 1024; l += 256) at[l] = g_attn[(size_t)bh * 1024 + l];
    __syncthreads();

    const float* vbase = g_qkv + ((size_t)b * QKV3 + 512 + h * DH) * N_ + n;
    float* obase = g_attnv + ((size_t)b * C_ + h * DH) * N_ + n;

    float acc[32] = {};
    #pragma unroll 4
    for (int j = 0; j < 32; j++) {
        float vj = vbase[(size_t)j * N_];
        #pragma unroll
        for (int i = 0; i < 32; i++) acc[i] += at[i * 32 + j] * vj;
    }
    #pragma unroll
    for (int i = 0; i < 32; i++) obase[(size_t)i * N_] = acc[i];
}

// ---------------- launch ----------------
extern "C" void kernel_launch(void* const* d_in, const int* in_sizes, int n_in,
                              void* d_out, int out_size) {
    const float* x     = (const float*)d_in[0];
    const float* gamma = (const float*)d_in[1];
    const float* beta  = (const float*)d_in[2];
    const float* Wqkv  = (const float*)d_in[3];
    const float* temp  = (const float*)d_in[4];
    const float* Wout  = (const float*)d_in[5];
    const float* bout  = (const float*)d_in[6];
    float* out = (float*)d_out;
    (void)in_sizes; (void)n_in; (void)out_size;

    // 1. LayerNorm
    ln_kernel<<<dim3(N_ / 256, B_), 256>>>(x, gamma, beta);
    // 2. QKV projection: [768 x 4096] per batch
    gemm_kernel<<<dim3(N_ / 64, QKV3 / 64, B_), 256>>>(Wqkv, nullptr, QKV3, 0, nullptr);
    // 3. q/k row norms -> scales
    norm_kernel<<<dim3(C_, B_, 2), 128>>>(temp);
    // 4. sim + softmax -> attn
    sim_softmax_kernel<<<B_ * HEADS, 256>>>();
    // 5. attn @ v
    av_kernel<<<dim3(N_ / 256, B_ * HEADS), 256>>>();
    // 6. output projection + bias -> d_out [b, c, n]
    gemm_kernel<<<dim3(N_ / 64, C_ / 64, B_), 256>>>(Wout, bout, C_, 1, out);
}

// round 3
// speedup vs baseline: 2.0837x; 2.0837x over previous
#include <cuda_runtime.h>
#include <cuda_bf16.h>
#include <math.h>
#include <stdint.h>

#define B_    16
#define C_    256
#define N_    4096
#define HEADS 8
#define DH    32
#define QKV3  768
#define LN_EPS 1e-5f
#define L2_EPS 1e-12f
#define XC_SCALE 8.0f

// ---------------- scratch (static device globals; no allocation) ----------------
__device__ __nv_bfloat16 g_thi[(size_t)B_ * N_ * C_];   // LN'd x, transposed [b][n][c], hi part
__device__ __nv_bfloat16 g_tlo[(size_t)B_ * N_ * C_];   // lo residual
__device__ float g_qkv[(size_t)B_ * QKV3 * N_];          // [b][j][n] fp32
__device__ float g_qscale[B_ * C_];
__device__ float g_kscale[B_ * C_];
__device__ float g_simpart[4 * B_ * HEADS * DH * DH];
__device__ float g_attn[B_ * HEADS * DH * DH];
__device__ __nv_bfloat16 g_avhi[(size_t)B_ * N_ * C_];   // attn@v transposed [b][n][c]
__device__ __nv_bfloat16 g_avlo[(size_t)B_ * N_ * C_];
__device__ __nv_bfloat16 g_wqh[QKV3 * C_];               // Wqkv^T [j][k]
__device__ __nv_bfloat16 g_wql[QKV3 * C_];
__device__ __nv_bfloat16 g_woh[C_ * C_];                 // Wout^T [j][k]
__device__ __nv_bfloat16 g_wol[C_ * C_];

// ---------------- Kernel 1: fused LayerNorm + transpose + bf16 split ----------------
__global__ __launch_bounds__(256) void lnconv_kernel(const float* __restrict__ x,
                                                     const float* __restrict__ gamma,
                                                     const float* __restrict__ beta) {
    __shared__ float s[256][33];
    __shared__ float p1[8][32], p2[8][32];
    __shared__ float mu_s[32], rs_s[32];
    int tid = threadIdx.x;
    int b = blockIdx.y, n0 = blockIdx.x * 32;
    int nl = tid & 31, g = tid >> 5;

    float a1 = 0.f, a2 = 0.f;
    for (int c = g; c < 256; c += 8) {
        float v = x[((size_t)b * 256 + c) * 4096 + n0 + nl];
        s[c][nl] = v;
        a1 += v; a2 += v * v;
    }
    p1[g][nl] = a1; p2[g][nl] = a2;
    __syncthreads();
    if (tid < 32) {
        float s1 = 0.f, s2 = 0.f;
        #pragma unroll
        for (int gg = 0; gg < 8; gg++) { s1 += p1[gg][tid]; s2 += p2[gg][tid]; }
        float mu = s1 * (1.0f / 256.0f);
        float var = s2 * (1.0f / 256.0f) - mu * mu;
        mu_s[tid] = mu;
        rs_s[tid] = rsqrtf(var + LN_EPS);
    }
    __syncthreads();

    float gm = gamma[tid], bt = beta[tid];
    #pragma unroll 4
    for (int n = 0; n < 32; n++) {
        float v = (s[tid][n] - mu_s[n]) * rs_s[n] * gm + bt;
        __nv_bfloat16 h = __float2bfloat16(v);
        __nv_bfloat16 l = __float2bfloat16(v - __bfloat162float(h));
        size_t o = ((size_t)b * 4096 + n0 + n) * 256 + tid;
        g_thi[o] = h;
        g_tlo[o] = l;
    }
}

// ---------------- Kernel 2: weight transpose + split ----------------
// mode 0: Wqkv [256][768] -> g_wqh/g_wql [768][256]
// mode 1: Wout [256][256] -> g_woh/g_wol [256][256]
__global__ void wsplit_kernel(const float* __restrict__ W, int mode) {
    __shared__ float tb[32][33];
    int K = 256;
    int M = (mode == 0) ? QKV3 : C_;
    __nv_bfloat16* hi = (mode == 0) ? g_wqh : g_woh;
    __nv_bfloat16* lo = (mode == 0) ? g_wql : g_wol;
    int tx = threadIdx.x, ty = threadIdx.y;
    int m0 = blockIdx.x * 32, k0 = blockIdx.y * 32;
    for (int r = ty; r < 32; r += 8)
        tb[r][tx] = W[(size_t)(k0 + r) * M + m0 + tx];
    __syncthreads();
    for (int r = ty; r < 32; r += 8) {
        float v = tb[tx][r];
        __nv_bfloat16 h = __float2bfloat16(v);
        __nv_bfloat16 l = __float2bfloat16(v - __bfloat162float(h));
        size_t o = (size_t)(m0 + r) * K + k0 + tx;
        hi[o] = h; lo[o] = l;
    }
}

// ---------------- Kernel 3: split-bf16 HMMA GEMM (mma.sync) ----------------
// D[n][j] = sum_k A[n][k]*B[j][k], written transposed to C[b][j][n] (+bias)
// mode 0: A=g_thi/lo, B=g_wqh/l -> g_qkv (Mtotal=768)
// mode 1: A=g_avhi/lo, B=g_woh/l -> out  (Mtotal=256, bias)
#define ASTR 40   // bf16 per smem row (32 data + 8 pad) -> conflict-free frags

__device__ __forceinline__ void mma_bf16(float* c, const uint32_t* a, const uint32_t* b) {
    asm volatile("mma.sync.aligned.m16n8k16.row.col.f32.bf16.bf16.f32 "
                 "{%0,%1,%2,%3}, {%4,%5,%6,%7}, {%8,%9}, {%0,%1,%2,%3};"
                 : "+f"(c[0]), "+f"(c[1]), "+f"(c[2]), "+f"(c[3])
                 : "r"(a[0]), "r"(a[1]), "r"(a[2]), "r"(a[3]), "r"(b[0]), "r"(b[1]));
}

__global__ __launch_bounds__(256) void mgemm_kernel(int mode, float* __restrict__ out_ext,
                                                    const float* __restrict__ bias, int Mtotal) {
    __shared__ __nv_bfloat16 As[2][128 * ASTR];
    __shared__ __nv_bfloat16 Bs[2][128 * ASTR];

    int tid = threadIdx.x, wid = tid >> 5, lane = tid & 31;
    int qrow = lane >> 2, qcol = lane & 3;
    int warp_m = wid >> 2;            // 0..1 -> 64 n-rows each
    int warp_n = wid & 3;             // 0..3 -> 32 j-cols each
    int n0 = blockIdx.x * 128, j0 = blockIdx.y * 128, b = blockIdx.z;

    const uint2* Agh = (const uint2*)(mode == 0 ? g_thi : g_avhi);
    const uint2* Agl = (const uint2*)(mode == 0 ? g_tlo : g_avlo);
    const uint2* Bgh = (const uint2*)(mode == 0 ? g_wqh : g_woh);
    const uint2* Bgl = (const uint2*)(mode == 0 ? g_wql : g_wol);
    float* C = (mode == 0) ? g_qkv : out_ext;

    float acc[4][4][4] = {};

    uint2* as0 = (uint2*)As[0]; uint2* as1 = (uint2*)As[1];
    uint2* bs0 = (uint2*)Bs[0]; uint2* bs1 = (uint2*)Bs[1];

    for (int chunk = 0; chunk < 8; chunk++) {       // K = 256, 32 per chunk
        #pragma unroll
        for (int it = 0; it < 4; it++) {
            int t = tid + it * 256;                 // 0..1023
            int row = t >> 3, u = t & 7;            // 8B x 8 = 32 bf16 per row
            size_t ga = ((size_t)(b * 4096 + n0 + row)) * 64 + chunk * 8 + u;
            size_t gb = ((size_t)(j0 + row)) * 64 + chunk * 8 + u;
            int so = row * (ASTR / 4) + u;          // uint2 index, stride 10
            as0[so] = Agh[ga];
            as1[so] = Agl[ga];
            bs0[so] = Bgh[gb];
            bs1[so] = Bgl[gb];
        }
        __syncthreads();

        const uint32_t* ah32 = (const uint32_t*)As[0];
        const uint32_t* al32 = (const uint32_t*)As[1];
        const uint32_t* bh32 = (const uint32_t*)Bs[0];
        const uint32_t* bl32 = (const uint32_t*)Bs[1];

        #pragma unroll
        for (int kk = 0; kk < 2; kk++) {            // two k16 steps
            uint32_t ah[4][4], al[4][4], bh[4][2], bl[4][2];
            #pragma unroll
            for (int mf = 0; mf < 4; mf++) {
                int r = (warp_m * 64 + mf * 16 + qrow) * (ASTR / 2) + kk * 8 + qcol;
                ah[mf][0] = ah32[r];            al[mf][0] = al32[r];
                ah[mf][1] = ah32[r + 8 * (ASTR / 2)]; al[mf][1] = al32[r + 8 * (ASTR / 2)];
                ah[mf][2] = ah32[r + 4];        al[mf][2] = al32[r + 4];
                ah[mf][3] = ah32[r + 8 * (ASTR / 2) + 4]; al[mf][3] = al32[r + 8 * (ASTR / 2) + 4];
            }
            #pragma unroll
            for (int nf = 0; nf < 4; nf++) {
                int r = (warp_n * 32 + nf * 8 + qrow) * (ASTR / 2) + kk * 8 + qcol;
                bh[nf][0] = bh32[r];     bl[nf][0] = bl32[r];
                bh[nf][1] = bh32[r + 4]; bl[nf][1] = bl32[r + 4];
            }
            #pragma unroll
            for (int mf = 0; mf < 4; mf++)
                #pragma unroll
                for (int nf = 0; nf < 4; nf++) {
                    mma_bf16(acc[mf][nf], ah[mf], bh[nf]);
                    mma_bf16(acc[mf][nf], ah[mf], bl[nf]);
                    mma_bf16(acc[mf][nf], al[mf], bh[nf]);
                }
        }
        __syncthreads();
    }

    // store transposed: element (m, jj) -> C[b][j0+jj][n0+m]
    #pragma unroll
    for (int mf = 0; mf < 4; mf++) {
        int m = n0 + warp_m * 64 + mf * 16 + qrow;
        #pragma unroll
        for (int nf = 0; nf < 4; nf++) {
            int j = j0 + warp_n * 32 + nf * 8 + qcol * 2;
            float b0 = bias ? bias[j] : 0.f;
            float b1 = bias ? bias[j + 1] : 0.f;
            size_t r0 = ((size_t)b * Mtotal + j) * 4096 + m;
            size_t r1 = r0 + 4096;                 // j+1
            C[r0]     = acc[mf][nf][0] + b0;
            C[r1]     = acc[mf][nf][1] + b1;
            C[r0 + 8] = acc[mf][nf][2] + b0;
            C[r1 + 8] = acc[mf][nf][3] + b1;
        }
    }
}

// ---------------- Kernel 4: q/k row L2 norms -> scales ----------------
__global__ void norm_kernel(const float* __restrict__ temp) {
    int j = blockIdx.x, b = blockIdx.y, which = blockIdx.z;
    int tid = threadIdx.x;
    const float* row = g_qkv + ((size_t)b * QKV3 + which * 256 + j) * N_;
    float s = 0.f;
    for (int n = tid * 4; n < N_; n += 512) {
        float4 v = *(const float4*)&row[n];
        s += v.x * v.x + v.y * v.y + v.z * v.z + v.w * v.w;
    }
    #pragma unroll
    for (int o = 16; o > 0; o >>= 1) s += __shfl_down_sync(0xffffffffu, s, o);
    __shared__ float ws[4];
    if ((tid & 31) == 0) ws[tid >> 5] = s;
    __syncthreads();
    if (tid == 0) {
        float tot = ws[0] + ws[1] + ws[2] + ws[3];
        float d = fmaxf(sqrtf(tot), L2_EPS);
        float sc = (which == 0) ? (expf(temp[j >> 5]) / d) : (1.0f / d);
        if (which == 0) g_qscale[b * C_ + j] = sc;
        else            g_kscale[b * C_ + j] = sc;
    }
}

// ---------------- Kernel 5: sim partials (split-K x4) ----------------
#define CHN 128
#define PAD 132
__global__ void sim_part_kernel() {
    __shared__ float qs[32 * PAD];
    __shared__ float ks[32 * PAD];
    __shared__ float simbuf[32 * 32];

    int bh = blockIdx.x, z = blockIdx.y;
    int b = bh >> 3, h = bh & 7;
    int tid = threadIdx.x;
    const float* qbase = g_qkv + ((size_t)b * QKV3 + h * DH) * N_;
    const float* kbase = g_qkv + ((size_t)b * QKV3 + 256 + h * DH) * N_;

    for (int l = tid; l < 1024; l += 256) simbuf[l] = 0.f;

    int g = tid >> 6;
    int p = tid & 63;
    int ii0 = (p >> 3) * 4;
    int jj0 = (p & 7) * 4;
    float acc[4][4] = {};

    int nstart = z * 1024, nend = nstart + 1024;
    for (int n0 = nstart; n0 < nend; n0 += CHN) {
        for (int e = tid * 4; e < 32 * CHN; e += 1024) {
            int row = e >> 7, t = e & (CHN - 1);
            *(float4*)&qs[row * PAD + t] = *(const float4*)&qbase[(size_t)row * N_ + n0 + t];
            *(float4*)&ks[row * PAD + t] = *(const float4*)&kbase[(size_t)row * N_ + n0 + t];
        }
        __syncthreads();
        int tb = g * 32;
        #pragma unroll
        for (int s = 0; s < 8; s++) {
            int t = tb + s * 4;
            float4 qv[4], kv[4];
            #pragma unroll
            for (int r = 0; r < 4; r++) qv[r] = *(const float4*)&qs[(ii0 + r) * PAD + t];
            #pragma unroll
            for (int c = 0; c < 4; c++) kv[c] = *(const float4*)&ks[(jj0 + c) * PAD + t];
            #pragma unroll
            for (int r = 0; r < 4; r++)
                #pragma unroll
                for (int c = 0; c < 4; c++)
                    acc[r][c] += qv[r].x * kv[c].x + qv[r].y * kv[c].y
                               + qv[r].z * kv[c].z + qv[r].w * kv[c].w;
        }
        __syncthreads();
    }

    #pragma unroll
    for (int r = 0; r < 4; r++)
        #pragma unroll
        for (int c = 0; c < 4; c++)
            atomicAdd(&simbuf[(ii0 + r) * 32 + jj0 + c], acc[r][c]);
    __syncthreads();

    float* dst = g_simpart + ((size_t)(z * 128 + bh)) * 1024;
    for (int l = tid; l < 1024; l += 256) dst[l] = simbuf[l];
}

// ---------------- Kernel 6: reduce partials + softmax -> attn ----------------
__global__ void softmax_kernel() {
    int bh = blockIdx.x;
    int i = threadIdx.x;
    int b = bh >> 3, h = bh & 7;
    float qsc = g_qscale[b * C_ + h * DH + i];
    float row[32];
    float mx = -1e30f;
    #pragma unroll 4
    for (int j = 0; j < 32; j++) {
        float v = 0.f;
        #pragma unroll
        for (int z = 0; z < 4; z++)
            v += g_simpart[((size_t)(z * 128 + bh)) * 1024 + i * 32 + j];
        v = v * qsc * g_kscale[b * C_ + h * DH + j] * XC_SCALE;
        row[j] = v;
        mx = fmaxf(mx, v);
    }
    float sum = 0.f;
    #pragma unroll
    for (int j = 0; j < 32; j++) { row[j] = expf(row[j] - mx); sum += row[j]; }
    float inv = 1.0f / sum;
    #pragma unroll
    for (int j = 0; j < 32; j++)
        g_attn[((size_t)bh * 32 + i) * 32 + j] = row[j] * inv;
}

// ---------------- Kernel 7: attn @ v, fused transpose + bf16 split ----------------
__global__ __launch_bounds__(256) void av_kernel() {
    __shared__ float at[1024];
    __shared__ float tb[32][257];
    int bh = blockIdx.y;
    int b = bh >> 3, h = bh & 7;
    int tid = threadIdx.x;
    int n = blockIdx.x * 256 + tid;

    for (int l = tid; l < 1024; l += 256) at[l] = g_attn[(size_t)bh * 1024 + l];
    __syncthreads();

    const float* vbase = g_qkv + ((size_t)b * QKV3 + 512 + h * DH) * N_ + n;

    float acc[32] = {};
    #pragma unroll 4
    for (int j = 0; j < 32; j++) {
        float vj = vbase[(size_t)j * N_];
        #pragma unroll
        for (int i = 0; i < 32; i++) acc[i] += at[i * 32 + j] * vj;
    }
    #pragma unroll
    for (int i = 0; i < 32; i++) tb[i][tid] = acc[i];
    __syncthreads();

    unsigned* outh = (unsigned*)g_avhi;
    unsigned* outl = (unsigned*)g_avlo;
    for (int l = tid; l < 4096; l += 256) {
        int nl = l >> 4, u = l & 15;
        float v0 = tb[u * 2 + 0][nl];
        float v1 = tb[u * 2 + 1][nl];
        __nv_bfloat16 h0 = __float2bfloat16(v0);
        __nv_bfloat16 h1 = __float2bfloat16(v1);
        __nv_bfloat16 l0 = __float2bfloat16(v0 - __bfloat162float(h0));
        __nv_bfloat16 l1 = __float2bfloat16(v1 - __bfloat162float(h1));
        int gn = blockIdx.x * 256 + nl;
        size_t idx = ((size_t)(b * 4096 + gn)) * 128 + h * 16 + u;
        outh[idx] = (unsigned)__bfloat16_as_ushort(h0) | ((unsigned)__bfloat16_as_ushort(h1) << 16);
        outl[idx] = (unsigned)__bfloat16_as_ushort(l0) | ((unsigned)__bfloat16_as_ushort(l1) << 16);
    }
}

// ---------------- launch ----------------
extern "C" void kernel_launch(void* const* d_in, const int* in_sizes, int n_in,
                              void* d_out, int out_size) {
    const float* x     = (const float*)d_in[0];
    const float* gamma = (const float*)d_in[1];
    const float* beta  = (const float*)d_in[2];
    const float* Wqkv  = (const float*)d_in[3];
    const float* temp  = (const float*)d_in[4];
    const float* Wout  = (const float*)d_in[5];
    const float* bout  = (const float*)d_in[6];
    float* out = (float*)d_out;
    (void)in_sizes; (void)n_in; (void)out_size;

    // 1. LN + transpose + bf16 split
    lnconv_kernel<<<dim3(N_ / 32, B_), 256>>>(x, gamma, beta);
    // 2. weight prep
    wsplit_kernel<<<dim3(QKV3 / 32, C_ / 32), dim3(32, 8)>>>(Wqkv, 0);
    wsplit_kernel<<<dim3(C_ / 32, C_ / 32), dim3(32, 8)>>>(Wout, 1);
    // 3. QKV projection (HMMA)
    mgemm_kernel<<<dim3(N_ / 128, QKV3 / 128, B_), 256>>>(0, nullptr, nullptr, QKV3);
    // 4. q/k norms
    norm_kernel<<<dim3(C_, B_, 2), 128>>>(temp);
    // 5. sim partials + softmax
    sim_part_kernel<<<dim3(B_ * HEADS, 4), 256>>>();
    softmax_kernel<<<B_ * HEADS, 32>>>();
    // 6. attn @ v
    av_kernel<<<dim3(N_ / 256, B_ * HEADS), 256>>>();
    // 7. output projection (HMMA) + bias -> d_out
    mgemm_kernel<<<dim3(N_ / 128, C_ / 128, B_), 256>>>(1, out, bout, C_);
}

// round 5
// speedup vs baseline: 2.4957x; 1.1977x over previous
#include <cuda_runtime.h>
#include <cuda_bf16.h>
#include <math.h>
#include <stdint.h>

#define B_    16
#define C_    256
#define N_    4096
#define HEADS 8
#define DH    32
#define QKV3  768
#define LN_EPS 1e-5f
#define L2_EPS 1e-12f
#define XC_SCALE 8.0f
#define ZSPLIT 8

// ---------------- scratch ----------------
__device__ __nv_bfloat16 g_thi[(size_t)B_ * N_ * C_];
__device__ __nv_bfloat16 g_tlo[(size_t)B_ * N_ * C_];
__device__ float g_qkv[(size_t)B_ * QKV3 * N_];
__device__ float g_qscale[B_ * C_];
__device__ float g_kscale[B_ * C_];
__device__ float g_simpart[ZSPLIT * B_ * HEADS * DH * DH];
__device__ float g_attn[B_ * HEADS * DH * DH];
__device__ __nv_bfloat16 g_avhi[(size_t)B_ * N_ * C_];
__device__ __nv_bfloat16 g_avlo[(size_t)B_ * N_ * C_];
__device__ __nv_bfloat16 g_wqh[QKV3 * C_];
__device__ __nv_bfloat16 g_wql[QKV3 * C_];
__device__ __nv_bfloat16 g_woh[C_ * C_];
__device__ __nv_bfloat16 g_wol[C_ * C_];

__device__ __forceinline__ uint32_t smem_u32(const void* p) {
    uint32_t a;
    asm("{ .reg .u64 t; cvta.to.shared.u64 t, %1; cvt.u32.u64 %0, t; }" : "=r"(a) : "l"(p));
    return a;
}
__device__ __forceinline__ void mma_bf16(float* c, const uint32_t* a, const uint32_t* b) {
    asm volatile("mma.sync.aligned.m16n8k16.row.col.f32.bf16.bf16.f32 "
                 "{%0,%1,%2,%3}, {%4,%5,%6,%7}, {%8,%9}, {%0,%1,%2,%3};"
                 : "+f"(c[0]), "+f"(c[1]), "+f"(c[2]), "+f"(c[3])
                 : "r"(a[0]), "r"(a[1]), "r"(a[2]), "r"(a[3]), "r"(b[0]), "r"(b[1]));
}
__device__ __forceinline__ void ldsm4(uint32_t* r, uint32_t addr) {
    asm volatile("ldmatrix.sync.aligned.m8n8.x4.shared.b16 {%0,%1,%2,%3}, [%4];"
                 : "=r"(r[0]), "=r"(r[1]), "=r"(r[2]), "=r"(r[3]) : "r"(addr));
}
__device__ __forceinline__ void cp16(uint32_t sa, const void* ga) {
    asm volatile("cp.async.cg.shared.global [%0], [%1], 16;" :: "r"(sa), "l"(ga) : "memory");
}
#define CP_COMMIT() asm volatile("cp.async.commit_group;" ::: "memory")
#define CP_WAIT1()  asm volatile("cp.async.wait_group 1;" ::: "memory")
#define CP_WAIT0()  asm volatile("cp.async.wait_group 0;" ::: "memory")

// ---------------- Kernel 1: fused LayerNorm + transpose + bf16 split ----------------
__global__ __launch_bounds__(256) void lnconv_kernel(const float* __restrict__ x,
                                                     const float* __restrict__ gamma,
                                                     const float* __restrict__ beta) {
    __shared__ float s[256][33];
    __shared__ float p1[8][32], p2[8][32];
    __shared__ float mu_s[32], rs_s[32];
    int tid = threadIdx.x;
    int b = blockIdx.y, n0 = blockIdx.x * 32;
    int nl = tid & 31, g = tid >> 5;

    float a1 = 0.f, a2 = 0.f;
    for (int c = g; c < 256; c += 8) {
        float v = x[((size_t)b * 256 + c) * 4096 + n0 + nl];
        s[c][nl] = v;
        a1 += v; a2 += v * v;
    }
    p1[g][nl] = a1; p2[g][nl] = a2;
    __syncthreads();
    if (tid < 32) {
        float s1 = 0.f, s2 = 0.f;
        #pragma unroll
        for (int gg = 0; gg < 8; gg++) { s1 += p1[gg][tid]; s2 += p2[gg][tid]; }
        float mu = s1 * (1.0f / 256.0f);
        float var = s2 * (1.0f / 256.0f) - mu * mu;
        mu_s[tid] = mu;
        rs_s[tid] = rsqrtf(var + LN_EPS);
    }
    __syncthreads();

    float gm = gamma[tid], bt = beta[tid];
    #pragma unroll 4
    for (int n = 0; n < 32; n++) {
        float v = (s[tid][n] - mu_s[n]) * rs_s[n] * gm + bt;
        __nv_bfloat16 h = __float2bfloat16(v);
        __nv_bfloat16 l = __float2bfloat16(v - __bfloat162float(h));
        size_t o = ((size_t)b * 4096 + n0 + n) * 256 + tid;
        g_thi[o] = h;
        g_tlo[o] = l;
    }
}

// ---------------- Kernel 2: weight transpose + split ----------------
__global__ void wsplit_kernel(const float* __restrict__ W, int mode) {
    __shared__ float tb[32][33];
    int K = 256;
    int M = (mode == 0) ? QKV3 : C_;
    __nv_bfloat16* hi = (mode == 0) ? g_wqh : g_woh;
    __nv_bfloat16* lo = (mode == 0) ? g_wql : g_wol;
    int tx = threadIdx.x, ty = threadIdx.y;
    int m0 = blockIdx.x * 32, k0 = blockIdx.y * 32;
    for (int r = ty; r < 32; r += 8)
        tb[r][tx] = W[(size_t)(k0 + r) * M + m0 + tx];
    __syncthreads();
    for (int r = ty; r < 32; r += 8) {
        float v = tb[tx][r];
        __nv_bfloat16 h = __float2bfloat16(v);
        __nv_bfloat16 l = __float2bfloat16(v - __bfloat162float(h));
        size_t o = (size_t)(m0 + r) * K + k0 + tx;
        hi[o] = h; lo[o] = l;
    }
}

// ---------------- Kernel 3: pipelined ldmatrix split-bf16 HMMA GEMM ----------------
// Block tile 128(n-rows m) x 128(j). K = 256 in 8 chunks of 32. 2-stage cp.async.
// smem per stage: Ah 8K | Al 8K | Bh 8K | Bl 8K = 32K; 2 stages = 64K dynamic.
// swizzle: within a tile row (64B = 4x16B chunks): chunk' = chunk ^ ((row>>1)&3)
#define STG 32768

__global__ __launch_bounds__(256) void mgemm_kernel(int mode, float* __restrict__ out_ext,
                                                    const float* __restrict__ bias, int Mtotal) {
    extern __shared__ char sm[];
    uint32_t smb = smem_u32(sm);

    int tid = threadIdx.x, wid = tid >> 5, lane = tid & 31;
    int qrow = lane >> 2, qcol = lane & 3;
    int warp_m = wid >> 2;            // 0..1 (64 rows)
    int warp_n = wid & 3;             // 0..3 (32 cols)
    int n0 = blockIdx.x * 128, j0 = blockIdx.y * 128, b = blockIdx.z;

    const uint4* Agh = (const uint4*)(mode == 0 ? g_thi : g_avhi);
    const uint4* Agl = (const uint4*)(mode == 0 ? g_tlo : g_avlo);
    const uint4* Bgh = (const uint4*)(mode == 0 ? g_wqh : g_woh);
    const uint4* Bgl = (const uint4*)(mode == 0 ? g_wql : g_wol);
    float* C = (mode == 0) ? g_qkv : out_ext;

    // loader mapping: 2 iters x 256 threads = 512 x 16B per matrix per stage
    int lr0 = tid >> 2;            // row for iter 0 (0..63)
    int lc = tid & 3;              // chunk
    // per-row swizzled byte offsets for the two rows this thread loads
    uint32_t so0 = (uint32_t)(lr0 * 64 + ((lc ^ ((lr0 >> 1) & 3)) * 16));
    int lr1 = lr0 + 64;
    uint32_t so1 = (uint32_t)(lr1 * 64 + ((lc ^ ((lr1 >> 1) & 3)) * 16));

    float acc[4][4][4] = {};

    // prologue: load chunk 0 into stage 0
    {
        size_t ga0 = ((size_t)(b * 4096 + n0 + lr0)) * 32 + lc;
        size_t ga1 = ((size_t)(b * 4096 + n0 + lr1)) * 32 + lc;
        size_t gb0 = ((size_t)(j0 + lr0)) * 32 + lc;
        size_t gb1 = ((size_t)(j0 + lr1)) * 32 + lc;
        cp16(smb + so0,                 Agh + ga0);
        cp16(smb + so1,                 Agh + ga1);
        cp16(smb + 8192 + so0,          Agl + ga0);
        cp16(smb + 8192 + so1,          Agl + ga1);
        cp16(smb + 16384 + so0,         Bgh + gb0);
        cp16(smb + 16384 + so1,         Bgh + gb1);
        cp16(smb + 24576 + so0,         Bgl + gb0);
        cp16(smb + 24576 + so1,         Bgl + gb1);
        CP_COMMIT();
    }

    // per-lane ldmatrix row/col mapping
    int aRow = (lane & 15);            // + warp_m*64 + mf*16
    int aCol = lane >> 4;              // 0..1
    int bRow = ((lane >> 4) << 3) + (lane & 7);   // + warp_n*32 + np*16
    int bCol = (lane >> 3) & 1;

    for (int chunk = 0; chunk < 8; chunk++) {
        if (chunk < 7) {
            int k8 = (chunk + 1) * 4;  // uint4 offset into 256-k row (32 uint4/row)
            uint32_t st = smb + ((chunk + 1) & 1) * STG;
            size_t ga0 = ((size_t)(b * 4096 + n0 + lr0)) * 32 + k8 + lc;
            size_t ga1 = ((size_t)(b * 4096 + n0 + lr1)) * 32 + k8 + lc;
            size_t gb0 = ((size_t)(j0 + lr0)) * 32 + k8 + lc;
            size_t gb1 = ((size_t)(j0 + lr1)) * 32 + k8 + lc;
            cp16(st + so0,          Agh + ga0);
            cp16(st + so1,          Agh + ga1);
            cp16(st + 8192 + so0,   Agl + ga0);
            cp16(st + 8192 + so1,   Agl + ga1);
            cp16(st + 16384 + so0,  Bgh + gb0);
            cp16(st + 16384 + so1,  Bgh + gb1);
            cp16(st + 24576 + so0,  Bgl + gb0);
            cp16(st + 24576 + so1,  Bgl + gb1);
            CP_COMMIT();
            CP_WAIT1();
        } else {
            CP_WAIT0();
        }
        __syncthreads();

        uint32_t st = smb + (chunk & 1) * STG;
        #pragma unroll
        for (int kk = 0; kk < 2; kk++) {
            uint32_t bh[2][4], bl[2][4];
            #pragma unroll
            for (int np = 0; np < 2; np++) {
                int row = warp_n * 32 + np * 16 + bRow;
                uint32_t cc = (uint32_t)(((kk * 2) | bCol) ^ ((row >> 1) & 3));
                uint32_t ad = st + 16384 + (uint32_t)(row * 64) + cc * 16;
                ldsm4(bh[np], ad);
                ldsm4(bl[np], ad + 8192);
            }
            #pragma unroll
            for (int mf = 0; mf < 4; mf++) {
                int row = warp_m * 64 + mf * 16 + aRow;
                uint32_t cc = (uint32_t)(((kk * 2) | aCol) ^ ((row >> 1) & 3));
                uint32_t ad = st + (uint32_t)(row * 64) + cc * 16;
                uint32_t ah[4], al[4];
                ldsm4(ah, ad);
                ldsm4(al, ad + 8192);
                #pragma unroll
                for (int nf = 0; nf < 4; nf++) {
                    const uint32_t* bhf = &bh[nf >> 1][(nf & 1) * 2];
                    const uint32_t* blf = &bl[nf >> 1][(nf & 1) * 2];
                    mma_bf16(acc[mf][nf], ah, bhf);
                    mma_bf16(acc[mf][nf], ah, blf);
                    mma_bf16(acc[mf][nf], al, bhf);
                }
            }
        }
        __syncthreads();
    }

    // store transposed: element (m, jj) -> C[b][j0+jj][n0+m]
    #pragma unroll
    for (int mf = 0; mf < 4; mf++) {
        int m = n0 + warp_m * 64 + mf * 16 + qrow;
        #pragma unroll
        for (int nf = 0; nf < 4; nf++) {
            int j = j0 + warp_n * 32 + nf * 8 + qcol * 2;
            float b0 = bias ? bias[j] : 0.f;
            float b1 = bias ? bias[j + 1] : 0.f;
            size_t r0 = ((size_t)b * Mtotal + j) * 4096 + m;
            size_t r1 = r0 + 4096;
            C[r0]     = acc[mf][nf][0] + b0;
            C[r1]     = acc[mf][nf][1] + b1;
            C[r0 + 8] = acc[mf][nf][2] + b0;
            C[r1 + 8] = acc[mf][nf][3] + b1;
        }
    }
}

// ---------------- Kernel 4: q/k row L2 norms -> scales ----------------
__global__ void norm_kernel(const float* __restrict__ temp) {
    int j = blockIdx.x, b = blockIdx.y, which = blockIdx.z;
    int tid = threadIdx.x;
    const float* row = g_qkv + ((size_t)b * QKV3 + which * 256 + j) * N_;
    float s = 0.f;
    for (int n = tid * 4; n < N_; n += 512) {
        float4 v = *(const float4*)&row[n];
        s += v.x * v.x + v.y * v.y + v.z * v.z + v.w * v.w;
    }
    #pragma unroll
    for (int o = 16; o > 0; o >>= 1) s += __shfl_down_sync(0xffffffffu, s, o);
    __shared__ float ws[4];
    if ((tid & 31) == 0) ws[tid >> 5] = s;
    __syncthreads();
    if (tid == 0) {
        float tot = ws[0] + ws[1] + ws[2] + ws[3];
        float d = fmaxf(sqrtf(tot), L2_EPS);
        float sc = (which == 0) ? (expf(temp[j >> 5]) / d) : (1.0f / d);
        if (which == 0) g_qscale[b * C_ + j] = sc;
        else            g_kscale[b * C_ + j] = sc;
    }
}

// ---------------- Kernel 5: sim partials (split-K x ZSPLIT) ----------------
#define CHN 128
#define PAD 132
__global__ void sim_part_kernel() {
    __shared__ float qs[32 * PAD];
    __shared__ float ks[32 * PAD];
    __shared__ float simbuf[32 * 32];

    int bh = blockIdx.x, z = blockIdx.y;
    int b = bh >> 3, h = bh & 7;
    int tid = threadIdx.x;
    const float* qbase = g_qkv + ((size_t)b * QKV3 + h * DH) * N_;
    const float* kbase = g_qkv + ((size_t)b * QKV3 + 256 + h * DH) * N_;

    for (int l = tid; l < 1024; l += 256) simbuf[l] = 0.f;

    int g = tid >> 6;
    int p = tid & 63;
    int ii0 = (p >> 3) * 4;
    int jj0 = (p & 7) * 4;
    float acc[4][4] = {};

    int nstart = z * (N_ / ZSPLIT), nend = nstart + (N_ / ZSPLIT);
    for (int n0 = nstart; n0 < nend; n0 += CHN) {
        for (int e = tid * 4; e < 32 * CHN; e += 1024) {
            int row = e >> 7, t = e & (CHN - 1);
            *(float4*)&qs[row * PAD + t] = *(const float4*)&qbase[(size_t)row * N_ + n0 + t];
            *(float4*)&ks[row * PAD + t] = *(const float4*)&kbase[(size_t)row * N_ + n0 + t];
        }
        __syncthreads();
        int tb = g * 32;
        #pragma unroll
        for (int s = 0; s < 8; s++) {
            int t = tb + s * 4;
            float4 qv[4], kv[4];
            #pragma unroll
            for (int r = 0; r < 4; r++) qv[r] = *(const float4*)&qs[(ii0 + r) * PAD + t];
            #pragma unroll
            for (int c = 0; c < 4; c++) kv[c] = *(const float4*)&ks[(jj0 + c) * PAD + t];
            #pragma unroll
            for (int r = 0; r < 4; r++)
                #pragma unroll
                for (int c = 0; c < 4; c++)
                    acc[r][c] += qv[r].x * kv[c].x + qv[r].y * kv[c].y
                               + qv[r].z * kv[c].z + qv[r].w * kv[c].w;
        }
        __syncthreads();
    }

    #pragma unroll
    for (int r = 0; r < 4; r++)
        #pragma unroll
        for (int c = 0; c < 4; c++)
            atomicAdd(&simbuf[(ii0 + r) * 32 + jj0 + c], acc[r][c]);
    __syncthreads();

    float* dst = g_simpart + ((size_t)(z * 128 + bh)) * 1024;
    for (int l = tid; l < 1024; l += 256) dst[l] = simbuf[l];
}

// ---------------- Kernel 6: reduce partials + softmax -> attn ----------------
__global__ void softmax_kernel() {
    int bh = blockIdx.x;
    int i = threadIdx.x;
    int b = bh >> 3, h = bh & 7;
    float qsc = g_qscale[b * C_ + h * DH + i];
    float row[32];
    float mx = -1e30f;
    #pragma unroll 4
    for (int j = 0; j < 32; j++) {
        float v = 0.f;
        #pragma unroll
        for (int z = 0; z < ZSPLIT; z++)
            v += g_simpart[((size_t)(z * 128 + bh)) * 1024 + i * 32 + j];
        v = v * qsc * g_kscale[b * C_ + h * DH + j] * XC_SCALE;
        row[j] = v;
        mx = fmaxf(mx, v);
    }
    float sum = 0.f;
    #pragma unroll
    for (int j = 0; j < 32; j++) { row[j] = expf(row[j] - mx); sum += row[j]; }
    float inv = 1.0f / sum;
    #pragma unroll
    for (int j = 0; j < 32; j++)
        g_attn[((size_t)bh * 32 + i) * 32 + j] = row[j] * inv;
}

// ---------------- Kernel 7: attn @ v, fused transpose + bf16 split ----------------
__global__ __launch_bounds__(256) void av_kernel() {
    __shared__ float at[1024];
    __shared__ float tb[32][257];
    int bh = blockIdx.y;
    int b = bh >> 3, h = bh & 7;
    int tid = threadIdx.x;
    int n = blockIdx.x * 256 + tid;

    for (int l = tid; l < 1024; l += 256) at[l] = g_attn[(size_t)bh * 1024 + l];
    __syncthreads();

    const float* vbase = g_qkv + ((size_t)b * QKV3 + 512 + h * DH) * N_ + n;

    float acc[32] = {};
    #pragma unroll 4
    for (int j = 0; j < 32; j++) {
        float vj = vbase[(size_t)j * N_];
        #pragma unroll
        for (int i = 0; i < 32; i++) acc[i] += at[i * 32 + j] * vj;
    }
    #pragma unroll
    for (int i = 0; i < 32; i++) tb[i][tid] = acc[i];
    __syncthreads();

    unsigned* outh = (unsigned*)g_avhi;
    unsigned* outl = (unsigned*)g_avlo;
    for (int l = tid; l < 4096; l += 256) {
        int nl = l >> 4, u = l & 15;
        float v0 = tb[u * 2 + 0][nl];
        float v1 = tb[u * 2 + 1][nl];
        __nv_bfloat16 h0 = __float2bfloat16(v0);
        __nv_bfloat16 h1 = __float2bfloat16(v1);
        __nv_bfloat16 l0 = __float2bfloat16(v0 - __bfloat162float(h0));
        __nv_bfloat16 l1 = __float2bfloat16(v1 - __bfloat162float(h1));
        int gn = blockIdx.x * 256 + nl;
        size_t idx = ((size_t)(b * 4096 + gn)) * 128 + h * 16 + u;
        outh[idx] = (unsigned)__bfloat16_as_ushort(h0) | ((unsigned)__bfloat16_as_ushort(h1) << 16);
        outl[idx] = (unsigned)__bfloat16_as_ushort(l0) | ((unsigned)__bfloat16_as_ushort(l1) << 16);
    }
}

// ---------------- launch ----------------
extern "C" void kernel_launch(void* const* d_in, const int* in_sizes, int n_in,
                              void* d_out, int out_size) {
    const float* x     = (const float*)d_in[0];
    const float* gamma = (const float*)d_in[1];
    const float* beta  = (const float*)d_in[2];
    const float* Wqkv  = (const float*)d_in[3];
    const float* temp  = (const float*)d_in[4];
    const float* Wout  = (const float*)d_in[5];
    const float* bout  = (const float*)d_in[6];
    float* out = (float*)d_out;
    (void)in_sizes; (void)n_in; (void)out_size;

    cudaFuncSetAttribute(mgemm_kernel, cudaFuncAttributeMaxDynamicSharedMemorySize, 2 * STG);

    // 1. LN + transpose + bf16 split
    lnconv_kernel<<<dim3(N_ / 32, B_), 256>>>(x, gamma, beta);
    // 2. weight prep
    wsplit_kernel<<<dim3(QKV3 / 32, C_ / 32), dim3(32, 8)>>>(Wqkv, 0);
    wsplit_kernel<<<dim3(C_ / 32, C_ / 32), dim3(32, 8)>>>(Wout, 1);
    // 3. QKV projection (pipelined HMMA)
    mgemm_kernel<<<dim3(N_ / 128, QKV3 / 128, B_), 256, 2 * STG>>>(0, nullptr, nullptr, QKV3);
    // 4. q/k norms
    norm_kernel<<<dim3(C_, B_, 2), 128>>>(temp);
    // 5. sim partials + softmax
    sim_part_kernel<<<dim3(B_ * HEADS, ZSPLIT), 256>>>();
    softmax_kernel<<<B_ * HEADS, 32>>>();
    // 6. attn @ v
    av_kernel<<<dim3(N_ / 256, B_ * HEADS), 256>>>();
    // 7. output projection (pipelined HMMA) + bias -> d_out
    mgemm_kernel<<<dim3(N_ / 128, C_ / 128, B_), 256, 2 * STG>>>(1, out, bout, C_);
}